// round 1
// baseline (speedup 1.0000x reference)
#include <cuda_runtime.h>
#include <math.h>

// Problem dims
#define Bb 2
#define Nn 2048
#define Ff 1024
#define Hh 16
#define Dd 64
#define OUTN 4194304ULL          /* B*N*H*D  : start of kv region in d_out */
#define KVPLANE 131072ULL        /* N*D per (b,h) plane */

// Scratch (static device globals; no runtime allocation)
__device__ float g_S[(size_t)Bb * Hh * Nn * Nn];   // 512 MB score/attn tensor [b][h][i][j]
__device__ float g_Q[(size_t)Bb * Hh * Nn * Dd];   // 16 MB  q (pre-scaled by D^-0.5) [b][h][n][d]
__device__ float g_O[(size_t)Bb * Nn * Hh * Dd];   // 16 MB  attn@v, laid out [b][n][h][d]

// ---------------------------------------------------------------------------
// Kernel 1: QKV projection. C[m, r] = sum_k x[m,k] * wqkv[r,k]
//   M = B*N = 4096, N = 3*H*D = 3072, K = F = 1024.
//   Epilogue scatters r -> (h, d, c) with c = qkv (innermost of the reshape):
//     r = h*192 + d*3 + c
//   q  -> g_Q (scaled by 1/8), k -> d_out kv[0], v -> d_out kv[1].
// ---------------------------------------------------------------------------
__global__ __launch_bounds__(256) void k_qkv(const float* __restrict__ x,
                                             const float* __restrict__ wqkv,
                                             float* __restrict__ out)
{
    __shared__ float As[32][132];
    __shared__ float Bs[32][132];
    const int t  = threadIdx.x;
    const int tx = t & 15, ty = t >> 4;
    const int m0 = blockIdx.y * 128;
    const int n0 = blockIdx.x * 128;

    float acc[8][8];
#pragma unroll
    for (int i = 0; i < 8; i++)
#pragma unroll
        for (int j = 0; j < 8; j++) acc[i][j] = 0.f;

    for (int kt = 0; kt < 1024; kt += 32) {
#pragma unroll
        for (int i = 0; i < 4; i++) {
            int idx = t + i * 256;
            int row = idx >> 3;
            int c4  = (idx & 7) * 4;
            float4 va = *(const float4*)(x + (size_t)(m0 + row) * 1024 + kt + c4);
            As[c4 + 0][row] = va.x; As[c4 + 1][row] = va.y;
            As[c4 + 2][row] = va.z; As[c4 + 3][row] = va.w;
            float4 vb = *(const float4*)(wqkv + (size_t)(n0 + row) * 1024 + kt + c4);
            Bs[c4 + 0][row] = vb.x; Bs[c4 + 1][row] = vb.y;
            Bs[c4 + 2][row] = vb.z; Bs[c4 + 3][row] = vb.w;
        }
        __syncthreads();
#pragma unroll
        for (int k = 0; k < 32; k++) {
            float a[8], b[8];
#pragma unroll
            for (int i = 0; i < 8; i++) a[i] = As[k][ty * 8 + i];
#pragma unroll
            for (int i = 0; i < 8; i++) b[i] = Bs[k][tx * 8 + i];
#pragma unroll
            for (int mi = 0; mi < 8; mi++)
#pragma unroll
                for (int ni = 0; ni < 8; ni++) acc[mi][ni] += a[mi] * b[ni];
        }
        __syncthreads();
    }

#pragma unroll
    for (int mi = 0; mi < 8; mi++) {
        int m  = m0 + ty * 8 + mi;
        int bb = m >> 11;
        int n  = m & 2047;
#pragma unroll
        for (int ni = 0; ni < 8; ni++) {
            int r   = n0 + tx * 8 + ni;
            int h   = r / 192;
            int rem = r - h * 192;
            int d   = rem / 3;
            int c   = rem - d * 3;
            float v = acc[mi][ni];
            if (c == 0) {
                g_Q[(((size_t)(bb * 16 + h)) * 2048 + n) * 64 + d] = v * 0.125f;
            } else {
                size_t kvidx = OUTN +
                    (((size_t)((c - 1) * 2 + bb) * 16 + h) * 2048 + n) * 64 + d;
                out[kvidx] = v;
            }
        }
    }
}

// ---------------------------------------------------------------------------
// Kernel 2: scores. Per (b,h): S = Q @ K^T (K = 64). S[b][h][i][j] in g_S.
// Q already carries the 1/sqrt(D) scale.
// ---------------------------------------------------------------------------
__global__ __launch_bounds__(256) void k_scores(const float* __restrict__ out)
{
    __shared__ float As[32][132];
    __shared__ float Bs[32][132];
    const int t  = threadIdx.x;
    const int tx = t & 15, ty = t >> 4;
    const int bh = blockIdx.z;
    const int m0 = blockIdx.y * 128;
    const int n0 = blockIdx.x * 128;

    const float* Q = g_Q + (size_t)bh * 2048 * 64;
    const float* K = out + OUTN + (size_t)bh * KVPLANE;   // kv[0][b][h]

    float acc[8][8];
#pragma unroll
    for (int i = 0; i < 8; i++)
#pragma unroll
        for (int j = 0; j < 8; j++) acc[i][j] = 0.f;

    for (int kt = 0; kt < 64; kt += 32) {
#pragma unroll
        for (int i = 0; i < 4; i++) {
            int idx = t + i * 256;
            int row = idx >> 3;
            int c4  = (idx & 7) * 4;
            float4 va = *(const float4*)(Q + (size_t)(m0 + row) * 64 + kt + c4);
            As[c4 + 0][row] = va.x; As[c4 + 1][row] = va.y;
            As[c4 + 2][row] = va.z; As[c4 + 3][row] = va.w;
            float4 vb = *(const float4*)(K + (size_t)(n0 + row) * 64 + kt + c4);
            Bs[c4 + 0][row] = vb.x; Bs[c4 + 1][row] = vb.y;
            Bs[c4 + 2][row] = vb.z; Bs[c4 + 3][row] = vb.w;
        }
        __syncthreads();
#pragma unroll
        for (int k = 0; k < 32; k++) {
            float a[8], b[8];
#pragma unroll
            for (int i = 0; i < 8; i++) a[i] = As[k][ty * 8 + i];
#pragma unroll
            for (int i = 0; i < 8; i++) b[i] = Bs[k][tx * 8 + i];
#pragma unroll
            for (int mi = 0; mi < 8; mi++)
#pragma unroll
                for (int ni = 0; ni < 8; ni++) acc[mi][ni] += a[mi] * b[ni];
        }
        __syncthreads();
    }

#pragma unroll
    for (int mi = 0; mi < 8; mi++) {
        float* Sp = g_S + ((size_t)bh * 2048 + (m0 + ty * 8 + mi)) * 2048 + n0 + tx * 8;
#pragma unroll
        for (int ni = 0; ni < 8; ni++) Sp[ni] = acc[mi][ni];
    }
}

// ---------------------------------------------------------------------------
// Kernel 3: fused premix (W_pre) + softmax + postmix (W_post).
// One CTA per (b, i): holds S[b, :, i, :] (16 x 2048 = 128KB) in smem.
// ---------------------------------------------------------------------------
__global__ __launch_bounds__(256) void k_mix(const float* __restrict__ wpre,
                                             const float* __restrict__ bpre,
                                             const float* __restrict__ wpost,
                                             const float* __restrict__ bpost)
{
    extern __shared__ float sm[];
    float* S  = sm;                // 16*2048
    float* Wa = sm + 16 * 2048;    // 256
    float* Wb = Wa + 256;          // 256
    float* ba = Wb + 256;          // 16
    float* bb2 = ba + 16;          // 16

    const int t  = threadIdx.x;
    const int bi = blockIdx.x;
    const int b  = bi >> 11;
    const int i  = bi & 2047;

    Wa[t] = wpre[t];
    Wb[t] = wpost[t];
    if (t < 16) { ba[t] = bpre[t]; bb2[t] = bpost[t]; }

    // load 16 head rows
    for (int h = 0; h < 16; h++) {
        const float* src = g_S + (((size_t)(b * 16 + h)) * 2048 + i) * 2048;
        float* dst = S + h * 2048;
        for (int j = t * 4; j < 2048; j += 1024)
            *(float4*)(dst + j) = *(const float4*)(src + j);
    }
    __syncthreads();

    // premix (in place, column-wise, no cross-thread hazard)
    for (int j = t; j < 2048; j += 256) {
        float sv[16];
#pragma unroll
        for (int h = 0; h < 16; h++) sv[h] = S[h * 2048 + j];
#pragma unroll
        for (int g = 0; g < 16; g++) {
            float a = ba[g];
#pragma unroll
            for (int h = 0; h < 16; h++) a += Wa[g * 16 + h] * sv[h];
            S[g * 2048 + j] = a;
        }
    }
    __syncthreads();

    // softmax per head row; warp w handles rows 2w, 2w+1
    const int w = t >> 5, lane = t & 31;
    for (int hh = 0; hh < 2; hh++) {
        float* row = S + (w * 2 + hh) * 2048;
        float m = -1e30f;
        for (int j = lane; j < 2048; j += 32) m = fmaxf(m, row[j]);
#pragma unroll
        for (int o = 16; o; o >>= 1) m = fmaxf(m, __shfl_xor_sync(0xffffffffu, m, o));
        float z = 0.f;
        for (int j = lane; j < 2048; j += 32) {
            float e = expf(row[j] - m);
            row[j] = e;
            z += e;
        }
#pragma unroll
        for (int o = 16; o; o >>= 1) z += __shfl_xor_sync(0xffffffffu, z, o);
        float inv = 1.f / z;
        for (int j = lane; j < 2048; j += 32) row[j] *= inv;
    }
    __syncthreads();

    // postmix, write back to global
    for (int j = t; j < 2048; j += 256) {
        float sv[16];
#pragma unroll
        for (int h = 0; h < 16; h++) sv[h] = S[h * 2048 + j];
#pragma unroll
        for (int g = 0; g < 16; g++) {
            float a = bb2[g];
#pragma unroll
            for (int h = 0; h < 16; h++) a += Wb[g * 16 + h] * sv[h];
            g_S[(((size_t)(b * 16 + g)) * 2048 + i) * 2048 + j] = a;
        }
    }
}

// ---------------------------------------------------------------------------
// Kernel 4: AV. Per (b,h): O = P(2048x2048) @ V(2048x64).
// Output written as g_O[b][n][h][d] (== (b, n, h*d) reshape for out proj).
// ---------------------------------------------------------------------------
__global__ __launch_bounds__(256) void k_av(const float* __restrict__ out)
{
    __shared__ float As[32][132];
    __shared__ float Bs[32][68];
    const int t  = threadIdx.x;
    const int tx = t & 15, ty = t >> 4;
    const int bh = blockIdx.z;
    const int m0 = blockIdx.y * 128;

    const float* P = g_S + (size_t)bh * 2048 * 2048;
    const float* V = out + OUTN + ((size_t)(bh + 32)) * KVPLANE;  // kv[1][b][h]

    float acc[8][4];
#pragma unroll
    for (int i = 0; i < 8; i++)
#pragma unroll
        for (int j = 0; j < 4; j++) acc[i][j] = 0.f;

    for (int kt = 0; kt < 2048; kt += 32) {
#pragma unroll
        for (int i = 0; i < 4; i++) {
            int idx = t + i * 256;
            int row = idx >> 3;
            int c4  = (idx & 7) * 4;
            float4 va = *(const float4*)(P + (size_t)(m0 + row) * 2048 + kt + c4);
            As[c4 + 0][row] = va.x; As[c4 + 1][row] = va.y;
            As[c4 + 2][row] = va.z; As[c4 + 3][row] = va.w;
        }
#pragma unroll
        for (int i = 0; i < 2; i++) {
            int idx = t + i * 256;
            int row = idx >> 4;
            int c4  = (idx & 15) * 4;
            *(float4*)&Bs[row][c4] = *(const float4*)(V + (size_t)(kt + row) * 64 + c4);
        }
        __syncthreads();
#pragma unroll
        for (int k = 0; k < 32; k++) {
            float a[8], b[4];
#pragma unroll
            for (int i = 0; i < 8; i++) a[i] = As[k][ty * 8 + i];
#pragma unroll
            for (int i = 0; i < 4; i++) b[i] = Bs[k][tx * 4 + i];
#pragma unroll
            for (int mi = 0; mi < 8; mi++)
#pragma unroll
                for (int ni = 0; ni < 4; ni++) acc[mi][ni] += a[mi] * b[ni];
        }
        __syncthreads();
    }

    const int b = bh >> 4, h = bh & 15;
#pragma unroll
    for (int mi = 0; mi < 8; mi++) {
        float* Op = g_O + (((size_t)b * 2048 + (m0 + ty * 8 + mi)) * 16 + h) * 64 + tx * 4;
#pragma unroll
        for (int ni = 0; ni < 4; ni++) Op[ni] = acc[mi][ni];
    }
}

// ---------------------------------------------------------------------------
// Kernel 5: output projection. C[m, f] = sum_k g_O[m,k] * wout[f,k].
//   M = 4096, N = 1024, K = 1024. Writes d_out[0 : 4194304].
// ---------------------------------------------------------------------------
__global__ __launch_bounds__(256) void k_out(const float* __restrict__ wout,
                                             float* __restrict__ out)
{
    __shared__ float As[32][132];
    __shared__ float Bs[32][132];
    const int t  = threadIdx.x;
    const int tx = t & 15, ty = t >> 4;
    const int m0 = blockIdx.y * 128;
    const int n0 = blockIdx.x * 128;

    float acc[8][8];
#pragma unroll
    for (int i = 0; i < 8; i++)
#pragma unroll
        for (int j = 0; j < 8; j++) acc[i][j] = 0.f;

    for (int kt = 0; kt < 1024; kt += 32) {
#pragma unroll
        for (int i = 0; i < 4; i++) {
            int idx = t + i * 256;
            int row = idx >> 3;
            int c4  = (idx & 7) * 4;
            float4 va = *(const float4*)(g_O + (size_t)(m0 + row) * 1024 + kt + c4);
            As[c4 + 0][row] = va.x; As[c4 + 1][row] = va.y;
            As[c4 + 2][row] = va.z; As[c4 + 3][row] = va.w;
            float4 vb = *(const float4*)(wout + (size_t)(n0 + row) * 1024 + kt + c4);
            Bs[c4 + 0][row] = vb.x; Bs[c4 + 1][row] = vb.y;
            Bs[c4 + 2][row] = vb.z; Bs[c4 + 3][row] = vb.w;
        }
        __syncthreads();
#pragma unroll
        for (int k = 0; k < 32; k++) {
            float a[8], b[8];
#pragma unroll
            for (int i = 0; i < 8; i++) a[i] = As[k][ty * 8 + i];
#pragma unroll
            for (int i = 0; i < 8; i++) b[i] = Bs[k][tx * 8 + i];
#pragma unroll
            for (int mi = 0; mi < 8; mi++)
#pragma unroll
                for (int ni = 0; ni < 8; ni++) acc[mi][ni] += a[mi] * b[ni];
        }
        __syncthreads();
    }

#pragma unroll
    for (int mi = 0; mi < 8; mi++) {
        float* Op = out + (size_t)(m0 + ty * 8 + mi) * 1024 + n0 + tx * 8;
#pragma unroll
        for (int ni = 0; ni < 8; ni++) Op[ni] = acc[mi][ni];
    }
}

// ---------------------------------------------------------------------------
extern "C" void kernel_launch(void* const* d_in, const int* in_sizes, int n_in,
                              void* d_out, int out_size)
{
    const float* x     = (const float*)d_in[0];
    const float* wqkv  = (const float*)d_in[1];
    const float* wout  = (const float*)d_in[2];
    const float* wpre  = (const float*)d_in[3];
    const float* bpre  = (const float*)d_in[4];
    const float* wpost = (const float*)d_in[5];
    const float* bpost = (const float*)d_in[6];
    float* out = (float*)d_out;

    // 1) QKV projection + scatter (q scaled, k/v straight into d_out kv region)
    k_qkv<<<dim3(24, 32), 256>>>(x, wqkv, out);

    // 2) scores per (b,h)
    k_scores<<<dim3(16, 16, 32), 256>>>(out);

    // 3) fused premix + softmax + postmix (one CTA per (b, query row))
    const int SM3 = (16 * 2048 + 544) * 4;  // 133,248 B dynamic smem
    cudaFuncSetAttribute(k_mix, cudaFuncAttributeMaxDynamicSharedMemorySize, SM3);
    k_mix<<<Bb * Nn, 256, SM3>>>(wpre, bpre, wpost, bpost);

    // 4) attn @ v
    k_av<<<dim3(1, 16, 32), 256>>>(out);

    // 5) output projection
    k_out<<<dim3(8, 32), 256>>>(wout, out);
}